// round 1
// baseline (speedup 1.0000x reference)
#include <cuda_runtime.h>
#include <math.h>

#define B_    16
#define N_    512
#define IN_   256
#define HID_  128
#define OUT_  256
#define K_    16
#define ROWS_ (B_*N_)   // 8192

// ---------------- scratch (device globals; no runtime allocation) ----------------
__device__ __align__(128) float g_W4  [IN_ * 4 * HID_];    // 256 x 512 packed [Wq|Wk|Wv|Wr]
__device__ __align__(128) float g_B4  [4 * HID_];          // 512 packed biases
__device__ __align__(128) float g_WMOD[HID_ * 2 * OUT_];   // 128 x 512 packed [Wc2 | Wc1-Wc2]
__device__ __align__(128) float g_QKVR[ROWS_ * 4 * HID_];  // 8192 x 512
__device__ __align__(128) float g_S   [B_ * N_ * N_];      // 16 x 512 x 512 attn logits
__device__ __align__(128) float g_H   [ROWS_ * HID_];      // 8192 x 128
__device__ __align__(128) float g_SQ  [ROWS_];             // ||h||^2
__device__ __align__(128) int   g_IDX [ROWS_ * K_];        // global row indices of 16 NN
__device__ __align__(128) float g_ZG  [ROWS_ * 2 * OUT_];  // 8192 x 512: [z | g]

// ---------------- weight packing ----------------
__global__ void pack_kernel(const float* __restrict__ Wq, const float* __restrict__ bq,
                            const float* __restrict__ Wk, const float* __restrict__ bk,
                            const float* __restrict__ Wv, const float* __restrict__ bv,
                            const float* __restrict__ Wr, const float* __restrict__ br,
                            const float* __restrict__ Wc,
                            float* __restrict__ W4, float* __restrict__ B4,
                            float* __restrict__ WMOD) {
    int t = blockIdx.x * blockDim.x + threadIdx.x;
    if (t < IN_ * 512) {
        int i = t >> 9, j = t & 511;
        int blk = j >> 7, h = j & 127;
        const float* src = (blk == 0) ? Wq : (blk == 1) ? Wk : (blk == 2) ? Wv : Wr;
        W4[t] = src[i * HID_ + h];
    }
    if (t < 512) {
        int blk = t >> 7, h = t & 127;
        const float* sb = (blk == 0) ? bq : (blk == 1) ? bk : (blk == 2) ? bv : br;
        B4[t] = sb[h];
    }
    if (t < HID_ * 512) {
        int d = t >> 9, o = t & 511;
        float w2 = Wc[(HID_ + d) * OUT_ + (o & 255)];
        WMOD[t] = (o < OUT_) ? w2 : (Wc[d * OUT_ + (o - OUT_)] - w2);
    }
}

// ---------------- generic 64x64 tiled fp32 GEMM (optionally B-transposed, batched) ----
template <bool TRANSB>
__global__ __launch_bounds__(256)
void gemm64(const float* __restrict__ A, int lda, long long sA,
            const float* __restrict__ Bm, int ldb, long long sB,
            float* __restrict__ C, int ldc, long long sC,
            int Kd, float alpha, const float* __restrict__ bias) {
    __shared__ float As[16][64];
    __shared__ float Bs[16][64];
    const float* Ab = A  + (long long)blockIdx.z * sA;
    const float* Bb = Bm + (long long)blockIdx.z * sB;
    float*       Cb = C  + (long long)blockIdx.z * sC;
    const int bm = blockIdx.y * 64;
    const int bn = blockIdx.x * 64;
    const int tid = threadIdx.x;
    const int tm = (tid >> 4) << 2;
    const int tn = (tid & 15) << 2;
    float acc[4][4] = {};
    for (int k0 = 0; k0 < Kd; k0 += 16) {
        {
            int m = tid >> 2, kq = (tid & 3) << 2;
            float4 a = *(const float4*)(Ab + (long long)(bm + m) * lda + k0 + kq);
            As[kq + 0][m] = a.x; As[kq + 1][m] = a.y;
            As[kq + 2][m] = a.z; As[kq + 3][m] = a.w;
        }
        if (TRANSB) {
            int nn = tid >> 2, kq = (tid & 3) << 2;
            float4 b = *(const float4*)(Bb + (long long)(bn + nn) * ldb + k0 + kq);
            Bs[kq + 0][nn] = b.x; Bs[kq + 1][nn] = b.y;
            Bs[kq + 2][nn] = b.z; Bs[kq + 3][nn] = b.w;
        } else {
            int kq = tid >> 4, nn = (tid & 15) << 2;
            *(float4*)&Bs[kq][nn] = *(const float4*)(Bb + (long long)(k0 + kq) * ldb + bn + nn);
        }
        __syncthreads();
#pragma unroll
        for (int kk = 0; kk < 16; kk++) {
            float4 av = *(const float4*)&As[kk][tm];
            float4 bv = *(const float4*)&Bs[kk][tn];
            float a[4] = {av.x, av.y, av.z, av.w};
            float b[4] = {bv.x, bv.y, bv.z, bv.w};
#pragma unroll
            for (int i = 0; i < 4; i++)
#pragma unroll
                for (int j = 0; j < 4; j++)
                    acc[i][j] = fmaf(a[i], b[j], acc[i][j]);
        }
        __syncthreads();
    }
    float bb[4] = {0.f, 0.f, 0.f, 0.f};
    if (bias) {
        float4 b4 = *(const float4*)(bias + bn + tn);
        bb[0] = b4.x; bb[1] = b4.y; bb[2] = b4.z; bb[3] = b4.w;
    }
#pragma unroll
    for (int i = 0; i < 4; i++) {
        float4 o;
        o.x = alpha * acc[i][0] + bb[0];
        o.y = alpha * acc[i][1] + bb[1];
        o.z = alpha * acc[i][2] + bb[2];
        o.w = alpha * acc[i][3] + bb[3];
        *(float4*)(Cb + (long long)(bm + tm + i) * ldc + bn + tn) = o;
    }
}

// ---------------- softmax + attn@V + residual, also emits ||h||^2 ----------------
__global__ __launch_bounds__(256)
void softmax_av_kernel(const float* __restrict__ S, const float* __restrict__ QKVR,
                       float* __restrict__ H, float* __restrict__ SQ) {
    __shared__ float P[16][512];    // 32 KB
    __shared__ float Vs[32][128];   // 16 KB
    const int b   = blockIdx.y;
    const int n0  = blockIdx.x * 16;
    const int tid = threadIdx.x;
    const int lane = tid & 31;
    const int w    = tid >> 5;      // 8 warps, warp w owns rows 2w, 2w+1
    const float* Sb = S + (long long)b * N_ * N_;

#pragma unroll
    for (int rr = 0; rr < 2; rr++) {
        const int r = 2 * w + rr;
        const float* srow = Sb + (long long)(n0 + r) * N_;
        float v[16];
        float mx = -INFINITY;
#pragma unroll
        for (int i = 0; i < 4; i++) {
            float4 t = *(const float4*)(srow + i * 128 + lane * 4);
            v[4*i+0] = t.x; v[4*i+1] = t.y; v[4*i+2] = t.z; v[4*i+3] = t.w;
            mx = fmaxf(mx, fmaxf(fmaxf(t.x, t.y), fmaxf(t.z, t.w)));
        }
#pragma unroll
        for (int off = 16; off; off >>= 1) mx = fmaxf(mx, __shfl_xor_sync(0xffffffffu, mx, off));
        float sum = 0.f;
#pragma unroll
        for (int i = 0; i < 16; i++) { v[i] = __expf(v[i] - mx); sum += v[i]; }
#pragma unroll
        for (int off = 16; off; off >>= 1) sum += __shfl_xor_sync(0xffffffffu, sum, off);
        float inv = 1.f / sum;
#pragma unroll
        for (int i = 0; i < 4; i++) {
            float4 t = make_float4(v[4*i]*inv, v[4*i+1]*inv, v[4*i+2]*inv, v[4*i+3]*inv);
            *(float4*)&P[r][i * 128 + lane * 4] = t;
        }
    }
    __syncthreads();

    const int tc = lane;
    const int tr = 2 * w;
    float acc[2][4] = {{0,0,0,0},{0,0,0,0}};
    for (int m0 = 0; m0 < N_; m0 += 32) {
#pragma unroll
        for (int i = 0; i < 4; i++) {
            int idx = tid + i * 256;
            int r = idx >> 5, c = (idx & 31) << 2;
            *(float4*)&Vs[r][c] =
                *(const float4*)(QKVR + (long long)(b * N_ + m0 + r) * (4 * HID_) + 2 * HID_ + c);
        }
        __syncthreads();
#pragma unroll
        for (int mt = 0; mt < 32; mt++) {
            float p0 = P[tr][m0 + mt];
            float p1 = P[tr + 1][m0 + mt];
            float4 vv = *(const float4*)&Vs[mt][tc << 2];
            acc[0][0] = fmaf(p0, vv.x, acc[0][0]); acc[0][1] = fmaf(p0, vv.y, acc[0][1]);
            acc[0][2] = fmaf(p0, vv.z, acc[0][2]); acc[0][3] = fmaf(p0, vv.w, acc[0][3]);
            acc[1][0] = fmaf(p1, vv.x, acc[1][0]); acc[1][1] = fmaf(p1, vv.y, acc[1][1]);
            acc[1][2] = fmaf(p1, vv.z, acc[1][2]); acc[1][3] = fmaf(p1, vv.w, acc[1][3]);
        }
        __syncthreads();
    }
#pragma unroll
    for (int rr = 0; rr < 2; rr++) {
        const long long row = (long long)(b * N_ + n0 + tr + rr);
        float4 rv = *(const float4*)(QKVR + row * (4 * HID_) + 3 * HID_ + (tc << 2));
        float h0 = acc[rr][0] + rv.x, h1 = acc[rr][1] + rv.y;
        float h2 = acc[rr][2] + rv.z, h3 = acc[rr][3] + rv.w;
        *(float4*)(H + row * HID_ + (tc << 2)) = make_float4(h0, h1, h2, h3);
        float sq = h0*h0 + h1*h1 + h2*h2 + h3*h3;
#pragma unroll
        for (int off = 16; off; off >>= 1) sq += __shfl_xor_sync(0xffffffffu, sq, off);
        if (lane == 0) SQ[row] = sq;
    }
}

// ---------------- Gram + top-16 nearest neighbors ----------------
// score_m = 2*h_n.h_m - ||h_m||^2  (= -dist + const per row; same ordering)
__global__ __launch_bounds__(256)
void topk_kernel(const float* __restrict__ H, const float* __restrict__ SQ,
                 int* __restrict__ IDX) {
    __shared__ float hN[16][128];     // 8 KB
    __shared__ float tile[64][132];   // 33.8 KB (pad 4 -> conflict-free lane-row LDS.128)
    const int b   = blockIdx.y;
    const int n0  = blockIdx.x * 16;
    const int tid = threadIdx.x;
    const int lane = tid & 31;
    const int w    = tid >> 5;       // 8 warps, warp owns rows 2w, 2w+1
    const int r0 = 2 * w, r1 = 2 * w + 1;

#pragma unroll
    for (int i = 0; i < 2; i++) {
        int idx = tid + i * 256;
        int r = idx >> 5, c = (idx & 31) << 2;
        *(float4*)&hN[r][c] = *(const float4*)(H + (long long)(b * N_ + n0 + r) * HID_ + c);
    }

    float cand0[16], cand1[16];
#pragma unroll
    for (int t = 0; t < 8; t++) {
        const int m0 = t * 64;
        __syncthreads();
#pragma unroll
        for (int i = 0; i < 8; i++) {
            int idx = tid + i * 256;
            int r = idx >> 5, c = (idx & 31) << 2;
            *(float4*)&tile[r][c] = *(const float4*)(H + (long long)(b * N_ + m0 + r) * HID_ + c);
        }
        __syncthreads();
#pragma unroll
        for (int j = 0; j < 2; j++) {
            const int m = j * 32 + lane;
            float dot0 = 0.f, dot1 = 0.f;
#pragma unroll 8
            for (int d4 = 0; d4 < 32; d4++) {
                float4 tv = *(const float4*)&tile[m][d4 << 2];
                float4 a0 = *(const float4*)&hN[r0][d4 << 2];
                float4 a1 = *(const float4*)&hN[r1][d4 << 2];
                dot0 = fmaf(a0.x, tv.x, dot0); dot0 = fmaf(a0.y, tv.y, dot0);
                dot0 = fmaf(a0.z, tv.z, dot0); dot0 = fmaf(a0.w, tv.w, dot0);
                dot1 = fmaf(a1.x, tv.x, dot1); dot1 = fmaf(a1.y, tv.y, dot1);
                dot1 = fmaf(a1.z, tv.z, dot1); dot1 = fmaf(a1.w, tv.w, dot1);
            }
            float sqm = SQ[b * N_ + m0 + m];
            cand0[t * 2 + j] = 2.f * dot0 - sqm;   // slot s -> m = (s<<5)|lane
            cand1[t * 2 + j] = 2.f * dot1 - sqm;
        }
    }

#pragma unroll
    for (int rr = 0; rr < 2; rr++) {
        const int n = n0 + 2 * w + rr;
        unsigned used = 0;
        for (int sel = 0; sel < K_; sel++) {
            float best = -INFINITY;
            int bslot = -1;
#pragma unroll
            for (int s = 0; s < 16; s++) {
                float cs = (rr == 0) ? cand0[s] : cand1[s];
                if (!((used >> s) & 1u) && cs > best) { best = cs; bslot = s; }
            }
            int   bm = (bslot >= 0) ? ((bslot << 5) | lane) : 0x3fffffff;
            float bv = best;
#pragma unroll
            for (int off = 16; off; off >>= 1) {
                float ov = __shfl_xor_sync(0xffffffffu, bv, off);
                int   om = __shfl_xor_sync(0xffffffffu, bm, off);
                if (ov > bv || (ov == bv && om < bm)) { bv = ov; bm = om; }
            }
            if ((bm & 31) == lane && (bm >> 5) < 16) used |= 1u << (bm >> 5);
            if (lane == 0) IDX[(long long)(b * N_ + n) * K_ + sel] = b * N_ + bm;
        }
    }
}

// ---------------- gather-max + layernorm + selu ----------------
__global__ __launch_bounds__(256)
void final_kernel(const float* __restrict__ ZG, const int* __restrict__ IDX,
                  const float* __restrict__ bc, const float* __restrict__ lnsc,
                  const float* __restrict__ lnbi, float* __restrict__ out) {
    const int n = blockIdx.x;
    const int o = threadIdx.x;
    const int lane = o & 31, w = o >> 5;
    __shared__ int   sidx[K_];
    __shared__ float red[8];
    __shared__ float sstat;
    if (o < K_) sidx[o] = IDX[n * K_ + o];
    __syncthreads();
    float v = -INFINITY;
#pragma unroll
    for (int k = 0; k < K_; k++) v = fmaxf(v, ZG[(long long)sidx[k] * 512 + o]);
    float y = v + ZG[(long long)n * 512 + OUT_ + o] + bc[o];
    // mean
    float s = y;
#pragma unroll
    for (int off = 16; off; off >>= 1) s += __shfl_xor_sync(0xffffffffu, s, off);
    if (lane == 0) red[w] = s;
    __syncthreads();
    if (o == 0) {
        float t = 0.f;
        for (int i = 0; i < 8; i++) t += red[i];
        sstat = t * (1.f / OUT_);
    }
    __syncthreads();
    const float mu = sstat;
    float d = y - mu;
    // variance (two-pass, matches reference)
    s = d * d;
#pragma unroll
    for (int off = 16; off; off >>= 1) s += __shfl_xor_sync(0xffffffffu, s, off);
    if (lane == 0) red[w] = s;
    __syncthreads();
    if (o == 0) {
        float t = 0.f;
        for (int i = 0; i < 8; i++) t += red[i];
        sstat = t * (1.f / OUT_);
    }
    __syncthreads();
    const float var = sstat;
    float nv = d * rsqrtf(var + 1e-5f) * lnsc[o] + lnbi[o];
    float r = nv > 0.f ? 1.0507009873554805f * nv
                       : 1.7580993408473766f * expm1f(nv);  // lambda*alpha
    out[(long long)n * OUT_ + o] = r;
}

// ---------------- launcher ----------------
extern "C" void kernel_launch(void* const* d_in, const int* in_sizes, int n_in,
                              void* d_out, int out_size) {
    const float* obj = (const float*)d_in[0];
    const float* Wq  = (const float*)d_in[2];
    const float* bq  = (const float*)d_in[3];
    const float* Wk  = (const float*)d_in[4];
    const float* bk  = (const float*)d_in[5];
    const float* Wv  = (const float*)d_in[6];
    const float* bv  = (const float*)d_in[7];
    const float* Wr  = (const float*)d_in[8];
    const float* br  = (const float*)d_in[9];
    const float* Wc  = (const float*)d_in[10];
    const float* bc  = (const float*)d_in[11];
    const float* lns = (const float*)d_in[12];
    const float* lnb = (const float*)d_in[13];
    float* out = (float*)d_out;

    float *W4, *B4, *WMOD, *QKVR, *S, *H, *SQ, *ZG;
    int* IDX;
    cudaGetSymbolAddress((void**)&W4,   g_W4);
    cudaGetSymbolAddress((void**)&B4,   g_B4);
    cudaGetSymbolAddress((void**)&WMOD, g_WMOD);
    cudaGetSymbolAddress((void**)&QKVR, g_QKVR);
    cudaGetSymbolAddress((void**)&S,    g_S);
    cudaGetSymbolAddress((void**)&H,    g_H);
    cudaGetSymbolAddress((void**)&SQ,   g_SQ);
    cudaGetSymbolAddress((void**)&IDX,  g_IDX);
    cudaGetSymbolAddress((void**)&ZG,   g_ZG);

    // 1) pack weights
    pack_kernel<<<512, 256>>>(Wq, bq, Wk, bk, Wv, bv, Wr, br, Wc, W4, B4, WMOD);
    // 2) QKVR = X @ [Wq|Wk|Wv|Wr] + bias   (8192x512x256)
    gemm64<false><<<dim3(8, 128, 1), 256>>>(obj, IN_, 0, W4, 512, 0,
                                            QKVR, 512, 0, IN_, 1.f, B4);
    // 3) S = (Q @ K^T) / sqrt(HID)   batched over 16
    gemm64<true><<<dim3(8, 8, B_), 256>>>(QKVR, 512, (long long)N_ * 512,
                                          QKVR + HID_, 512, (long long)N_ * 512,
                                          S, N_, (long long)N_ * N_,
                                          HID_, 0.08838834764831843f, nullptr);
    // 4) H = softmax(S) @ V + R ; SQ = ||h||^2
    softmax_av_kernel<<<dim3(N_ / 16, B_), 256>>>(S, QKVR, H, SQ);
    // 5) top-16 nearest neighbors per row
    topk_kernel<<<dim3(N_ / 16, B_), 256>>>(H, SQ, IDX);
    // 6) [z | g] = H @ [Wc2 | Wc1-Wc2]   (8192x512x128)
    gemm64<false><<<dim3(8, 128, 1), 256>>>(H, HID_, 0, WMOD, 512, 0,
                                            ZG, 512, 0, HID_, 1.f, nullptr);
    // 7) gather-max + LN + selu
    final_kernel<<<ROWS_, 256>>>(ZG, IDX, bc, lns, lnb, out);
}

// round 2
// speedup vs baseline: 1.0540x; 1.0540x over previous
#include <cuda_runtime.h>
#include <math.h>

#define B_    16
#define N_    512
#define IN_   256
#define HID_  128
#define OUT_  256
#define K_    16
#define ROWS_ (B_*N_)   // 8192

typedef unsigned long long u64;

// ---- packed f32x2 helpers (FFMA2: ptxas won't emit from C++, only via PTX) ----
__device__ __forceinline__ u64 pk2(float lo, float hi) {
    u64 r; asm("mov.b64 %0,{%1,%2};" : "=l"(r) : "f"(lo), "f"(hi)); return r;
}
__device__ __forceinline__ u64 dup2(float v) {
    u64 r; asm("mov.b64 %0,{%1,%1};" : "=l"(r) : "f"(v)); return r;
}
__device__ __forceinline__ void fma2(u64& d, u64 a, u64 b) {
    asm("fma.rn.f32x2 %0, %1, %2, %0;" : "+l"(d) : "l"(a), "l"(b));
}
__device__ __forceinline__ float2 upk(u64 v) {
    float2 f; asm("mov.b64 {%0,%1},%2;" : "=f"(f.x), "=f"(f.y) : "l"(v)); return f;
}

// ---------------- scratch (device globals; no runtime allocation) ----------------
__device__ __align__(128) float g_W4  [IN_ * 4 * HID_];    // 256 x 512 packed [Wq|Wk|Wv|Wr]
__device__ __align__(128) float g_B4  [4 * HID_];          // 512 packed biases
__device__ __align__(128) float g_WMOD[HID_ * 2 * OUT_];   // 128 x 512 packed [Wc2 | Wc1-Wc2]
__device__ __align__(128) float g_QKVR[ROWS_ * 4 * HID_];  // 8192 x 512
__device__ __align__(128) float g_S   [B_ * N_ * N_];      // 16 x 512 x 512 attn logits
__device__ __align__(128) float g_H   [ROWS_ * HID_];      // 8192 x 128
__device__ __align__(128) float g_SQ  [ROWS_];             // ||h||^2
__device__ __align__(128) int   g_IDX [ROWS_ * K_];        // global row indices of 16 NN
__device__ __align__(128) float g_ZG  [ROWS_ * 2 * OUT_];  // 8192 x 512: [z | g]

// ---------------- weight packing ----------------
__global__ void pack_kernel(const float* __restrict__ Wq, const float* __restrict__ bq,
                            const float* __restrict__ Wk, const float* __restrict__ bk,
                            const float* __restrict__ Wv, const float* __restrict__ bv,
                            const float* __restrict__ Wr, const float* __restrict__ br,
                            const float* __restrict__ Wc,
                            float* __restrict__ W4, float* __restrict__ B4,
                            float* __restrict__ WMOD) {
    int t = blockIdx.x * blockDim.x + threadIdx.x;
    if (t < IN_ * 512) {
        int i = t >> 9, j = t & 511;
        int blk = j >> 7, h = j & 127;
        const float* src = (blk == 0) ? Wq : (blk == 1) ? Wk : (blk == 2) ? Wv : Wr;
        W4[t] = src[i * HID_ + h];
    }
    if (t < 512) {
        int blk = t >> 7, h = t & 127;
        const float* sb = (blk == 0) ? bq : (blk == 1) ? bk : (blk == 2) ? bv : br;
        B4[t] = sb[h];
    }
    if (t < HID_ * 512) {
        int d = t >> 9, o = t & 511;
        float w2 = Wc[(HID_ + d) * OUT_ + (o & 255)];
        WMOD[t] = (o < OUT_) ? w2 : (Wc[d * OUT_ + (o - OUT_)] - w2);
    }
}

// ------- generic 64x64 tiled fp32 GEMM with FFMA2 (optionally B^T, batched) -------
template <bool TRANSB>
__global__ __launch_bounds__(256)
void gemm64(const float* __restrict__ A, int lda, long long sA,
            const float* __restrict__ Bm, int ldb, long long sB,
            float* __restrict__ C, int ldc, long long sC,
            int Kd, float alpha, const float* __restrict__ bias) {
    __shared__ float As[16][64];
    __shared__ float Bs[16][64];
    const float* Ab = A  + (long long)blockIdx.z * sA;
    const float* Bb = Bm + (long long)blockIdx.z * sB;
    float*       Cb = C  + (long long)blockIdx.z * sC;
    const int bm = blockIdx.y * 64;
    const int bn = blockIdx.x * 64;
    const int tid = threadIdx.x;
    const int tm = (tid >> 4) << 2;
    const int tn = (tid & 15) << 2;
    // acc[p][j] = ( C[tm+2p][tn+j] , C[tm+2p+1][tn+j] )
    u64 acc[2][4] = {};
    for (int k0 = 0; k0 < Kd; k0 += 16) {
        {
            int m = tid >> 2, kq = (tid & 3) << 2;
            float4 a = *(const float4*)(Ab + (long long)(bm + m) * lda + k0 + kq);
            As[kq + 0][m] = a.x; As[kq + 1][m] = a.y;
            As[kq + 2][m] = a.z; As[kq + 3][m] = a.w;
        }
        if (TRANSB) {
            int nn = tid >> 2, kq = (tid & 3) << 2;
            float4 b = *(const float4*)(Bb + (long long)(bn + nn) * ldb + k0 + kq);
            Bs[kq + 0][nn] = b.x; Bs[kq + 1][nn] = b.y;
            Bs[kq + 2][nn] = b.z; Bs[kq + 3][nn] = b.w;
        } else {
            int kq = tid >> 4, nn = (tid & 15) << 2;
            *(float4*)&Bs[kq][nn] = *(const float4*)(Bb + (long long)(k0 + kq) * ldb + bn + nn);
        }
        __syncthreads();
#pragma unroll
        for (int kk = 0; kk < 16; kk++) {
            float4 av = *(const float4*)&As[kk][tm];
            float4 bv = *(const float4*)&Bs[kk][tn];
            u64 a01 = pk2(av.x, av.y), a23 = pk2(av.z, av.w);
            u64 b0 = dup2(bv.x), b1 = dup2(bv.y), b2 = dup2(bv.z), b3 = dup2(bv.w);
            fma2(acc[0][0], a01, b0); fma2(acc[0][1], a01, b1);
            fma2(acc[0][2], a01, b2); fma2(acc[0][3], a01, b3);
            fma2(acc[1][0], a23, b0); fma2(acc[1][1], a23, b1);
            fma2(acc[1][2], a23, b2); fma2(acc[1][3], a23, b3);
        }
        __syncthreads();
    }
    float bb[4] = {0.f, 0.f, 0.f, 0.f};
    if (bias) {
        float4 b4 = *(const float4*)(bias + bn + tn);
        bb[0] = b4.x; bb[1] = b4.y; bb[2] = b4.z; bb[3] = b4.w;
    }
#pragma unroll
    for (int p = 0; p < 2; p++) {
        float2 f0 = upk(acc[p][0]), f1 = upk(acc[p][1]);
        float2 f2 = upk(acc[p][2]), f3 = upk(acc[p][3]);
        float4 o0, o1;
        o0.x = alpha * f0.x + bb[0]; o0.y = alpha * f1.x + bb[1];
        o0.z = alpha * f2.x + bb[2]; o0.w = alpha * f3.x + bb[3];
        o1.x = alpha * f0.y + bb[0]; o1.y = alpha * f1.y + bb[1];
        o1.z = alpha * f2.y + bb[2]; o1.w = alpha * f3.y + bb[3];
        *(float4*)(Cb + (long long)(bm + tm + 2 * p)     * ldc + bn + tn) = o0;
        *(float4*)(Cb + (long long)(bm + tm + 2 * p + 1) * ldc + bn + tn) = o1;
    }
}

// ------- softmax + attn@V + residual (+||h||^2), 4 warps x 4 rows, FFMA2 -------
__global__ __launch_bounds__(128)
void softmax_av_kernel(const float* __restrict__ S, const float* __restrict__ QKVR,
                       float* __restrict__ H, float* __restrict__ SQ) {
    __shared__ float P4[4][512][4];   // 32 KB: [warp][m][row-in-warp]
    __shared__ float Vs[32][128];     // 16 KB
    const int b    = blockIdx.y;
    const int n0   = blockIdx.x * 16;
    const int tid  = threadIdx.x;
    const int lane = tid & 31;
    const int w    = tid >> 5;        // 4 warps, warp owns rows 4w..4w+3
    const float* Sb = S + (long long)b * N_ * N_ + (long long)(n0 + 4 * w) * N_;

    // phase 1: per-row max & 1/sum
    float mxr[4], invr[4];
#pragma unroll
    for (int rr = 0; rr < 4; rr++) {
        const float* srow = Sb + rr * N_;
        float v[16];
        float mx = -INFINITY;
#pragma unroll
        for (int i = 0; i < 4; i++) {
            float4 t = *(const float4*)(srow + i * 128 + lane * 4);
            v[4*i+0] = t.x; v[4*i+1] = t.y; v[4*i+2] = t.z; v[4*i+3] = t.w;
            mx = fmaxf(mx, fmaxf(fmaxf(t.x, t.y), fmaxf(t.z, t.w)));
        }
#pragma unroll
        for (int off = 16; off; off >>= 1) mx = fmaxf(mx, __shfl_xor_sync(0xffffffffu, mx, off));
        float sum = 0.f;
#pragma unroll
        for (int i = 0; i < 16; i++) sum += __expf(v[i] - mx);
#pragma unroll
        for (int off = 16; off; off >>= 1) sum += __shfl_xor_sync(0xffffffffu, sum, off);
        mxr[rr] = mx; invr[rr] = 1.f / sum;
    }

    // phase 2: write P4 column-sliced (float4 over this warp's 4 rows)
#pragma unroll
    for (int k2 = 0; k2 < 16; k2++) {
        int m = lane + 32 * k2;
        float4 p;
        p.x = __expf(Sb[0 * N_ + m] - mxr[0]) * invr[0];
        p.y = __expf(Sb[1 * N_ + m] - mxr[1]) * invr[1];
        p.z = __expf(Sb[2 * N_ + m] - mxr[2]) * invr[2];
        p.w = __expf(Sb[3 * N_ + m] - mxr[3]) * invr[3];
        *(float4*)&P4[w][m][0] = p;
    }

    // phase 3: AV with FFMA2. lane owns cols lane*4..lane*4+3; acc over 4 rows.
    u64 acc[4][2] = {};
    const float* Vbase = QKVR + (long long)(b * N_) * 512 + 2 * HID_;
    for (int m0 = 0; m0 < N_; m0 += 32) {
#pragma unroll
        for (int i = 0; i < 8; i++) {
            int idx = tid + i * 128;
            int r = idx >> 5, c = (idx & 31) << 2;
            *(float4*)&Vs[r][c] = *(const float4*)(Vbase + (long long)(m0 + r) * 512 + c);
        }
        __syncthreads();
#pragma unroll
        for (int mt = 0; mt < 32; mt++) {
            float4 p4 = *(const float4*)&P4[w][m0 + mt][0];   // broadcast, 1 wavefront
            float4 vv = *(const float4*)&Vs[mt][lane << 2];
            u64 vp01 = pk2(vv.x, vv.y), vp23 = pk2(vv.z, vv.w);
            u64 d0 = dup2(p4.x), d1 = dup2(p4.y), d2 = dup2(p4.z), d3 = dup2(p4.w);
            fma2(acc[0][0], d0, vp01); fma2(acc[0][1], d0, vp23);
            fma2(acc[1][0], d1, vp01); fma2(acc[1][1], d1, vp23);
            fma2(acc[2][0], d2, vp01); fma2(acc[2][1], d2, vp23);
            fma2(acc[3][0], d3, vp01); fma2(acc[3][1], d3, vp23);
        }
        __syncthreads();
    }

    // epilogue: residual add, store H, ||h||^2
#pragma unroll
    for (int rr = 0; rr < 4; rr++) {
        const long long row = (long long)(b * N_ + n0 + 4 * w + rr);
        float4 rv = *(const float4*)(QKVR + row * 512 + 3 * HID_ + (lane << 2));
        float2 a01 = upk(acc[rr][0]), a23 = upk(acc[rr][1]);
        float h0 = a01.x + rv.x, h1 = a01.y + rv.y;
        float h2 = a23.x + rv.z, h3 = a23.y + rv.w;
        *(float4*)(H + row * HID_ + (lane << 2)) = make_float4(h0, h1, h2, h3);
        float sq = h0*h0 + h1*h1 + h2*h2 + h3*h3;
#pragma unroll
        for (int off = 16; off; off >>= 1) sq += __shfl_xor_sync(0xffffffffu, sq, off);
        if (lane == 0) SQ[row] = sq;
    }
}

// ---------------- Gram + top-16 nearest neighbors (FFMA2 dot products) ----------------
// score_m = 2*h_n.h_m - ||h_m||^2  (= -dist + const per row; same ordering)
__global__ __launch_bounds__(256)
void topk_kernel(const float* __restrict__ H, const float* __restrict__ SQ,
                 int* __restrict__ IDX) {
    __shared__ float hN[16][128];     // 8 KB
    __shared__ float tile[64][132];   // 33.8 KB (pad -> conflict-free)
    const int b    = blockIdx.y;
    const int n0   = blockIdx.x * 16;
    const int tid  = threadIdx.x;
    const int lane = tid & 31;
    const int w    = tid >> 5;       // 8 warps, warp owns rows 2w, 2w+1
    const int r0 = 2 * w, r1 = 2 * w + 1;

#pragma unroll
    for (int i = 0; i < 2; i++) {
        int idx = tid + i * 256;
        int r = idx >> 5, c = (idx & 31) << 2;
        *(float4*)&hN[r][c] = *(const float4*)(H + (long long)(b * N_ + n0 + r) * HID_ + c);
    }

    float cand0[16], cand1[16];
#pragma unroll
    for (int t = 0; t < 8; t++) {
        const int m0 = t * 64;
        __syncthreads();
#pragma unroll
        for (int i = 0; i < 8; i++) {
            int idx = tid + i * 256;
            int r = idx >> 5, c = (idx & 31) << 2;
            *(float4*)&tile[r][c] = *(const float4*)(H + (long long)(b * N_ + m0 + r) * HID_ + c);
        }
        __syncthreads();
#pragma unroll
        for (int j = 0; j < 2; j++) {
            const int m = j * 32 + lane;
            u64 q0a = 0, q0b = 0, q1a = 0, q1b = 0;
#pragma unroll 8
            for (int d4 = 0; d4 < 32; d4++) {
                float4 tv = *(const float4*)&tile[m][d4 << 2];
                float4 a0 = *(const float4*)&hN[r0][d4 << 2];
                float4 a1 = *(const float4*)&hN[r1][d4 << 2];
                u64 t01 = pk2(tv.x, tv.y), t23 = pk2(tv.z, tv.w);
                fma2(q0a, pk2(a0.x, a0.y), t01); fma2(q0b, pk2(a0.z, a0.w), t23);
                fma2(q1a, pk2(a1.x, a1.y), t01); fma2(q1b, pk2(a1.z, a1.w), t23);
            }
            float2 s0a = upk(q0a), s0b = upk(q0b), s1a = upk(q1a), s1b = upk(q1b);
            float dot0 = (s0a.x + s0a.y) + (s0b.x + s0b.y);
            float dot1 = (s1a.x + s1a.y) + (s1b.x + s1b.y);
            float sqm = SQ[b * N_ + m0 + m];
            cand0[t * 2 + j] = 2.f * dot0 - sqm;   // slot s -> m = (s<<5)|lane
            cand1[t * 2 + j] = 2.f * dot1 - sqm;
        }
    }

#pragma unroll
    for (int rr = 0; rr < 2; rr++) {
        const int n = n0 + 2 * w + rr;
        unsigned used = 0;
        for (int sel = 0; sel < K_; sel++) {
            float best = -INFINITY;
            int bslot = -1;
#pragma unroll
            for (int s = 0; s < 16; s++) {
                float cs = (rr == 0) ? cand0[s] : cand1[s];
                if (!((used >> s) & 1u) && cs > best) { best = cs; bslot = s; }
            }
            int   bm = (bslot >= 0) ? ((bslot << 5) | lane) : 0x3fffffff;
            float bv = best;
#pragma unroll
            for (int off = 16; off; off >>= 1) {
                float ov = __shfl_xor_sync(0xffffffffu, bv, off);
                int   om = __shfl_xor_sync(0xffffffffu, bm, off);
                if (ov > bv || (ov == bv && om < bm)) { bv = ov; bm = om; }
            }
            if ((bm & 31) == lane && (bm >> 5) < 16) used |= 1u << (bm >> 5);
            if (lane == 0) IDX[(long long)(b * N_ + n) * K_ + sel] = b * N_ + bm;
        }
    }
}

// ---------------- gather-max + layernorm + selu ----------------
__global__ __launch_bounds__(256)
void final_kernel(const float* __restrict__ ZG, const int* __restrict__ IDX,
                  const float* __restrict__ bc, const float* __restrict__ lnsc,
                  const float* __restrict__ lnbi, float* __restrict__ out) {
    const int n = blockIdx.x;
    const int o = threadIdx.x;
    const int lane = o & 31, w = o >> 5;
    __shared__ int   sidx[K_];
    __shared__ float red[8];
    __shared__ float sstat;
    if (o < K_) sidx[o] = IDX[n * K_ + o];
    __syncthreads();
    float v = -INFINITY;
#pragma unroll
    for (int k = 0; k < K_; k++) v = fmaxf(v, ZG[(long long)sidx[k] * 512 + o]);
    float y = v + ZG[(long long)n * 512 + OUT_ + o] + bc[o];
    float s = y;
#pragma unroll
    for (int off = 16; off; off >>= 1) s += __shfl_xor_sync(0xffffffffu, s, off);
    if (lane == 0) red[w] = s;
    __syncthreads();
    if (o == 0) {
        float t = 0.f;
        for (int i = 0; i < 8; i++) t += red[i];
        sstat = t * (1.f / OUT_);
    }
    __syncthreads();
    const float mu = sstat;
    float d = y - mu;
    s = d * d;
#pragma unroll
    for (int off = 16; off; off >>= 1) s += __shfl_xor_sync(0xffffffffu, s, off);
    if (lane == 0) red[w] = s;
    __syncthreads();
    if (o == 0) {
        float t = 0.f;
        for (int i = 0; i < 8; i++) t += red[i];
        sstat = t * (1.f / OUT_);
    }
    __syncthreads();
    const float var = sstat;
    float nv = d * rsqrtf(var + 1e-5f) * lnsc[o] + lnbi[o];
    float r = nv > 0.f ? 1.0507009873554805f * nv
                       : 1.7580993408473766f * expm1f(nv);
    out[(long long)n * OUT_ + o] = r;
}

// ---------------- launcher ----------------
extern "C" void kernel_launch(void* const* d_in, const int* in_sizes, int n_in,
                              void* d_out, int out_size) {
    const float* obj = (const float*)d_in[0];
    const float* Wq  = (const float*)d_in[2];
    const float* bq  = (const float*)d_in[3];
    const float* Wk  = (const float*)d_in[4];
    const float* bk  = (const float*)d_in[5];
    const float* Wv  = (const float*)d_in[6];
    const float* bv  = (const float*)d_in[7];
    const float* Wr  = (const float*)d_in[8];
    const float* br  = (const float*)d_in[9];
    const float* Wc  = (const float*)d_in[10];
    const float* bc  = (const float*)d_in[11];
    const float* lns = (const float*)d_in[12];
    const float* lnb = (const float*)d_in[13];
    float* out = (float*)d_out;

    float *W4, *B4, *WMOD, *QKVR, *S, *H, *SQ, *ZG;
    int* IDX;
    cudaGetSymbolAddress((void**)&W4,   g_W4);
    cudaGetSymbolAddress((void**)&B4,   g_B4);
    cudaGetSymbolAddress((void**)&WMOD, g_WMOD);
    cudaGetSymbolAddress((void**)&QKVR, g_QKVR);
    cudaGetSymbolAddress((void**)&S,    g_S);
    cudaGetSymbolAddress((void**)&H,    g_H);
    cudaGetSymbolAddress((void**)&SQ,   g_SQ);
    cudaGetSymbolAddress((void**)&IDX,  g_IDX);
    cudaGetSymbolAddress((void**)&ZG,   g_ZG);

    // 1) pack weights
    pack_kernel<<<512, 256>>>(Wq, bq, Wk, bk, Wv, bv, Wr, br, Wc, W4, B4, WMOD);
    // 2) QKVR = X @ [Wq|Wk|Wv|Wr] + bias   (8192x512x256)
    gemm64<false><<<dim3(8, 128, 1), 256>>>(obj, IN_, 0, W4, 512, 0,
                                            QKVR, 512, 0, IN_, 1.f, B4);
    // 3) S = (Q @ K^T) / sqrt(HID)   batched over 16
    gemm64<true><<<dim3(8, 8, B_), 256>>>(QKVR, 512, (long long)N_ * 512,
                                          QKVR + HID_, 512, (long long)N_ * 512,
                                          S, N_, (long long)N_ * N_,
                                          HID_, 0.08838834764831843f, nullptr);
    // 4) H = softmax(S) @ V + R ; SQ = ||h||^2
    softmax_av_kernel<<<dim3(N_ / 16, B_), 128>>>(S, QKVR, H, SQ);
    // 5) top-16 nearest neighbors per row
    topk_kernel<<<dim3(N_ / 16, B_), 256>>>(H, SQ, IDX);
    // 6) [z | g] = H @ [Wc2 | Wc1-Wc2]   (8192x512x128)
    gemm64<false><<<dim3(8, 128, 1), 256>>>(H, HID_, 0, WMOD, 512, 0,
                                            ZG, 512, 0, HID_, 1.f, nullptr);
    // 7) gather-max + LN + selu
    final_kernel<<<ROWS_, 256>>>(ZG, IDX, bc, lns, lnb, out);
}

// round 4
// speedup vs baseline: 1.9097x; 1.8118x over previous
#include <cuda_runtime.h>
#include <cuda_bf16.h>
#include <math.h>
#include <stdint.h>

#define B_    16
#define N_    512
#define IN_   256
#define HID_  128
#define OUT_  256
#define K_    16
#define ROWS_ (B_*N_)   // 8192

typedef __nv_bfloat16 bf16;

// ---------------- scratch (device globals; no runtime allocation) ----------------
__device__ __align__(128) bf16  g_Xh [ROWS_ * IN_],  g_Xl [ROWS_ * IN_];      // X split
__device__ __align__(128) bf16  g_W4h[512 * IN_],    g_W4l[512 * IN_];        // [Wq|Wk|Wv|Wr]^T
__device__ __align__(128) bf16  g_WMh[512 * HID_],   g_WMl[512 * HID_];       // [Wc2|Wc1-Wc2]^T
__device__ __align__(128) float g_B4 [512];
__device__ __align__(128) bf16  g_Qh [ROWS_ * HID_], g_Ql [ROWS_ * HID_];
__device__ __align__(128) bf16  g_Kh [ROWS_ * HID_], g_Kl [ROWS_ * HID_];
__device__ __align__(128) bf16  g_VTh[B_ * HID_ * N_], g_VTl[B_ * HID_ * N_]; // [b][d][m]
__device__ __align__(128) float g_R  [ROWS_ * HID_];
__device__ __align__(128) float g_S  [B_ * N_ * N_];                          // logits, then scores
__device__ __align__(128) bf16  g_Ph [B_ * N_ * N_], g_Pl [B_ * N_ * N_];
__device__ __align__(128) float g_H  [ROWS_ * HID_];
__device__ __align__(128) bf16  g_Hh [ROWS_ * HID_], g_Hl [ROWS_ * HID_];
__device__ __align__(128) float g_SQ [ROWS_];
__device__ __align__(128) int   g_IDX[ROWS_ * K_];
__device__ __align__(128) float g_ZG [ROWS_ * 512];

// ---------------- helpers ----------------
__device__ __forceinline__ uint32_t s2u(const void* p) {
    uint32_t a;
    asm("{ .reg .u64 t; cvta.to.shared.u64 t, %1; cvt.u32.u64 %0, t; }" : "=r"(a) : "l"(p));
    return a;
}
__device__ __forceinline__ void ldsm4(uint32_t* r, uint32_t addr) {
    asm volatile("ldmatrix.sync.aligned.m8n8.x4.shared.b16 {%0,%1,%2,%3}, [%4];"
                 : "=r"(r[0]), "=r"(r[1]), "=r"(r[2]), "=r"(r[3]) : "r"(addr));
}
__device__ __forceinline__ void ldsm2(uint32_t* r, uint32_t addr) {
    asm volatile("ldmatrix.sync.aligned.m8n8.x2.shared.b16 {%0,%1}, [%2];"
                 : "=r"(r[0]), "=r"(r[1]) : "r"(addr));
}
__device__ __forceinline__ void mma16816(float* c, const uint32_t* a, const uint32_t* b) {
    asm volatile("mma.sync.aligned.m16n8k16.row.col.f32.bf16.bf16.f32 "
                 "{%0,%1,%2,%3}, {%4,%5,%6,%7}, {%8,%9}, {%0,%1,%2,%3};"
                 : "+f"(c[0]), "+f"(c[1]), "+f"(c[2]), "+f"(c[3])
                 : "r"(a[0]), "r"(a[1]), "r"(a[2]), "r"(a[3]), "r"(b[0]), "r"(b[1]));
}
__device__ __forceinline__ void split2(float x, bf16& h, bf16& l) {
    h = __float2bfloat16_rn(x);
    l = __float2bfloat16_rn(x - __bfloat162float(h));
}

// ---------------- input conversion / weight packing ----------------
__global__ void convert_kernel(const float* __restrict__ X,
                               const float* __restrict__ Wq, const float* __restrict__ bq,
                               const float* __restrict__ Wk, const float* __restrict__ bk,
                               const float* __restrict__ Wv, const float* __restrict__ bv,
                               const float* __restrict__ Wr, const float* __restrict__ br,
                               const float* __restrict__ Wc) {
    int t = blockIdx.x * blockDim.x + threadIdx.x;
    if (t < ROWS_ * IN_) split2(X[t], g_Xh[t], g_Xl[t]);
    if (t < 512 * IN_) {          // W4T[o][i] = W_blk[i][o&127]
        int o = t >> 8, i = t & 255;
        int blk = o >> 7, h = o & 127;
        const float* W = (blk == 0) ? Wq : (blk == 1) ? Wk : (blk == 2) ? Wv : Wr;
        split2(W[i * HID_ + h], g_W4h[t], g_W4l[t]);
    }
    if (t < 512) {
        int blk = t >> 7, h = t & 127;
        const float* sb = (blk == 0) ? bq : (blk == 1) ? bk : (blk == 2) ? bv : br;
        g_B4[t] = sb[h];
    }
    if (t < 512 * HID_) {         // WMT[o][d]: o<256 -> Wc2, else Wc1-Wc2
        int o = t >> 7, d = t & 127;
        float w2 = Wc[(HID_ + d) * OUT_ + (o & 255)];
        float v  = (o < OUT_) ? w2 : (Wc[d * OUT_ + (o - OUT_)] - w2);
        split2(v, g_WMh[t], g_WMl[t]);
    }
}

// ---------------- unified mma.sync stage ----------------
// D[128x128] = A[128xK] * B[128xK]^T with bf16x3 splits, fp32 register accumulate.
// MODE: 0=QKVR  1=S  2=AV  3=GRAM  4=ZG
#define BK     64
#define LDS_   72                   // BK + 8 pad (bf16)
#define TILEB  (128 * LDS_ * 2)     // 18432 bytes per tile
#define SM_BYTES (4 * TILEB)        // 73728

template <int MODE>
__global__ void __launch_bounds__(256, 1) mma_stage() {
    extern __shared__ char smem[];
    const int tid = threadIdx.x, lane = tid & 31, w = tid >> 5;
    const int wm = w & 1, wn = w >> 1;           // 2 x 4 warp grid
    const int nT = blockIdx.x, mT = blockIdx.y, b = blockIdx.z;

    const bf16 *Ah, *Al, *Bh, *Bl;
    int Kd, lda, ldb;
    if (MODE == 0) {
        size_t ar = (size_t)mT * 128 * IN_;
        Ah = g_Xh + ar; Al = g_Xl + ar; lda = IN_;
        size_t br_ = (size_t)nT * 128 * IN_;
        Bh = g_W4h + br_; Bl = g_W4l + br_; ldb = IN_; Kd = IN_;
    } else if (MODE == 1) {
        size_t ar = ((size_t)b * N_ + mT * 128) * HID_;
        Ah = g_Qh + ar; Al = g_Ql + ar; lda = HID_;
        size_t br_ = ((size_t)b * N_ + nT * 128) * HID_;
        Bh = g_Kh + br_; Bl = g_Kl + br_; ldb = HID_; Kd = HID_;
    } else if (MODE == 2) {
        size_t ar = ((size_t)b * N_ + mT * 128) * N_;
        Ah = g_Ph + ar; Al = g_Pl + ar; lda = N_;
        size_t br_ = (size_t)b * HID_ * N_;
        Bh = g_VTh + br_; Bl = g_VTl + br_; ldb = N_; Kd = N_;
    } else if (MODE == 3) {
        size_t ar = ((size_t)b * N_ + mT * 128) * HID_;
        Ah = g_Hh + ar; Al = g_Hl + ar; lda = HID_;
        size_t br_ = ((size_t)b * N_ + nT * 128) * HID_;
        Bh = g_Hh + br_; Bl = g_Hl + br_; ldb = HID_; Kd = HID_;
    } else {
        size_t ar = (size_t)mT * 128 * HID_;
        Ah = g_Hh + ar; Al = g_Hl + ar; lda = HID_;
        size_t br_ = (size_t)nT * 128 * HID_;
        Bh = g_WMh + br_; Bl = g_WMl + br_; ldb = HID_; Kd = HID_;
    }

    bf16* sAh = (bf16*)(smem);
    bf16* sAl = (bf16*)(smem + TILEB);
    bf16* sBh = (bf16*)(smem + 2 * TILEB);
    bf16* sBl = (bf16*)(smem + 3 * TILEB);
    const uint32_t uAh = s2u(sAh), uAl = s2u(sAl), uBh = s2u(sBh), uBl = s2u(sBl);

    float acc[4][4][4] = {};

    const int nc = Kd / BK;
    for (int c = 0; c < nc; c++) {
        __syncthreads();
        const int k0 = c * BK;
#pragma unroll
        for (int i = 0; i < 4; i++) {
            int idx = tid + i * 256;          // 0..1023
            int r = idx >> 3, c8 = (idx & 7) << 3;
            int sdst = r * LDS_ + c8;
            *(uint4*)(sAh + sdst) = *(const uint4*)(Ah + (size_t)r * lda + k0 + c8);
            *(uint4*)(sAl + sdst) = *(const uint4*)(Al + (size_t)r * lda + k0 + c8);
            *(uint4*)(sBh + sdst) = *(const uint4*)(Bh + (size_t)r * ldb + k0 + c8);
            *(uint4*)(sBl + sdst) = *(const uint4*)(Bl + (size_t)r * ldb + k0 + c8);
        }
        __syncthreads();

        // per-lane ldmatrix address pieces
        const int arow = wm * 64 + (lane & 15);        // + i*16
        const int akof = ((lane >> 4) << 3);           // + ks*16
        const int brow = wn * 32 + (lane & 7);         // + j*8
        const int bkof = ((lane >> 3) & 1) << 3;       // + ks*16

#pragma unroll
        for (int ks = 0; ks < BK / 16; ks++) {
            const int kk = ks * 16;
            uint32_t aH[4][4], aL[4][4], bH[4][2], bL[4][2];
#pragma unroll
            for (int i = 0; i < 4; i++)
                ldsm4(aH[i], uAh + (uint32_t)(((arow + i * 16) * LDS_ + kk + akof) * 2));
#pragma unroll
            for (int j = 0; j < 4; j++)
                ldsm2(bH[j], uBh + (uint32_t)(((brow + j * 8) * LDS_ + kk + bkof) * 2));
#pragma unroll
            for (int i = 0; i < 4; i++)
#pragma unroll
                for (int j = 0; j < 4; j++) mma16816(acc[i][j], aH[i], bH[j]);
#pragma unroll
            for (int i = 0; i < 4; i++)
                ldsm4(aL[i], uAl + (uint32_t)(((arow + i * 16) * LDS_ + kk + akof) * 2));
#pragma unroll
            for (int i = 0; i < 4; i++)
#pragma unroll
                for (int j = 0; j < 4; j++) mma16816(acc[i][j], aL[i], bH[j]);
#pragma unroll
            for (int j = 0; j < 4; j++)
                ldsm2(bL[j], uBl + (uint32_t)(((brow + j * 8) * LDS_ + kk + bkof) * 2));
#pragma unroll
            for (int i = 0; i < 4; i++)
#pragma unroll
                for (int j = 0; j < 4; j++) mma16816(acc[i][j], aH[i], bL[j]);
        }
    }

    // ---------------- epilogue ----------------
    const int r_base = wm * 64 + (lane >> 2);
    const int c_base = wn * 32 + ((lane & 3) << 1);

    if (MODE == 0 && nT == 2) {
        // stage (with bias) then transposed write to VT[b][d][m]
        float* Cs = (float*)smem;   // [128][129]
        __syncthreads();
#pragma unroll
        for (int i = 0; i < 4; i++)
#pragma unroll
            for (int j = 0; j < 4; j++) {
                int r = r_base + i * 16, c = c_base + j * 8;
                Cs[r * 129 + c]           = acc[i][j][0] + g_B4[256 + c];
                Cs[r * 129 + c + 1]       = acc[i][j][1] + g_B4[256 + c + 1];
                Cs[(r + 8) * 129 + c]     = acc[i][j][2] + g_B4[256 + c];
                Cs[(r + 8) * 129 + c + 1] = acc[i][j][3] + g_B4[256 + c + 1];
            }
        __syncthreads();
        const int bb = mT >> 2, m0 = (mT & 3) * 128;
        const int d = tid >> 1, ms = (tid & 1) * 64;
        size_t base = ((size_t)bb * HID_ + d) * N_ + m0 + ms;
#pragma unroll 8
        for (int k = 0; k < 64; k++)
            split2(Cs[(ms + k) * 129 + d], g_VTh[base + k], g_VTl[base + k]);
        return;
    }

#pragma unroll
    for (int i = 0; i < 4; i++)
#pragma unroll
        for (int j = 0; j < 4; j++)
#pragma unroll
            for (int h = 0; h < 2; h++) {
                const int r = r_base + i * 16 + h * 8;
                const int c = c_base + j * 8;
                float v0 = acc[i][j][h * 2], v1 = acc[i][j][h * 2 + 1];
                if (MODE == 0) {
                    size_t grow = (size_t)mT * 128 + r;
                    if (nT == 0 || nT == 1) {
                        bf16* Dh = (nT == 0) ? g_Qh : g_Kh;
                        bf16* Dl = (nT == 0) ? g_Ql : g_Kl;
                        split2(v0 + g_B4[nT * 128 + c],     Dh[grow * HID_ + c],     Dl[grow * HID_ + c]);
                        split2(v1 + g_B4[nT * 128 + c + 1], Dh[grow * HID_ + c + 1], Dl[grow * HID_ + c + 1]);
                    } else {   // nT == 3 -> R
                        *(float2*)(g_R + grow * HID_ + c) =
                            make_float2(v0 + g_B4[384 + c], v1 + g_B4[384 + c + 1]);
                    }
                } else if (MODE == 1) {
                    size_t row = (size_t)b * N_ + mT * 128 + r;
                    *(float2*)(g_S + row * N_ + nT * 128 + c) =
                        make_float2(v0 * 0.08838834764831843f, v1 * 0.08838834764831843f);
                } else if (MODE == 2) {
                    size_t row = (size_t)b * N_ + mT * 128 + r;
                    float h0 = v0 + g_R[row * HID_ + c];
                    float h1 = v1 + g_R[row * HID_ + c + 1];
                    *(float2*)(g_H + row * HID_ + c) = make_float2(h0, h1);
                    split2(h0, g_Hh[row * HID_ + c],     g_Hl[row * HID_ + c]);
                    split2(h1, g_Hh[row * HID_ + c + 1], g_Hl[row * HID_ + c + 1]);
                } else if (MODE == 3) {
                    size_t row = (size_t)b * N_ + mT * 128 + r;
                    float s0 = 2.f * v0 - g_SQ[b * N_ + nT * 128 + c];
                    float s1 = 2.f * v1 - g_SQ[b * N_ + nT * 128 + c + 1];
                    *(float2*)(g_S + row * N_ + nT * 128 + c) = make_float2(s0, s1);
                } else {
                    size_t row = (size_t)mT * 128 + r;
                    *(float2*)(g_ZG + row * 512 + nT * 128 + c) = make_float2(v0, v1);
                }
            }
}

// ---------------- ||h||^2 per row ----------------
__global__ __launch_bounds__(256)
void sqnorm_kernel() {
    const int lane = threadIdx.x & 31, w = threadIdx.x >> 5;
    const size_t row = (size_t)blockIdx.x * 8 + w;
    float4 v = *(const float4*)(g_H + row * HID_ + lane * 4);
    float s = v.x * v.x + v.y * v.y + v.z * v.z + v.w * v.w;
#pragma unroll
    for (int off = 16; off; off >>= 1) s += __shfl_xor_sync(0xffffffffu, s, off);
    if (lane == 0) g_SQ[row] = s;
}

// ---------------- softmax: S -> P (bf16 hi/lo), warp per row ----------------
__global__ __launch_bounds__(256)
void softmax_kernel() {
    const int tid = threadIdx.x, lane = tid & 31, w = tid >> 5;
    const size_t row = (size_t)blockIdx.x * 8 + w;
    const float* srow = g_S + row * N_;
    float v[16];
    float mx = -INFINITY;
#pragma unroll
    for (int i = 0; i < 4; i++) {
        float4 t = *(const float4*)(srow + i * 128 + lane * 4);
        v[4*i+0] = t.x; v[4*i+1] = t.y; v[4*i+2] = t.z; v[4*i+3] = t.w;
        mx = fmaxf(mx, fmaxf(fmaxf(t.x, t.y), fmaxf(t.z, t.w)));
    }
#pragma unroll
    for (int off = 16; off; off >>= 1) mx = fmaxf(mx, __shfl_xor_sync(0xffffffffu, mx, off));
    float sum = 0.f;
#pragma unroll
    for (int i = 0; i < 16; i++) { v[i] = __expf(v[i] - mx); sum += v[i]; }
#pragma unroll
    for (int off = 16; off; off >>= 1) sum += __shfl_xor_sync(0xffffffffu, sum, off);
    float inv = 1.f / sum;
#pragma unroll
    for (int i = 0; i < 16; i++) v[i] *= inv;
#pragma unroll
    for (int i = 0; i < 4; i++) {
        size_t o = row * N_ + i * 128 + lane * 4;
#pragma unroll
        for (int j = 0; j < 4; j++) split2(v[4*i+j], g_Ph[o + j], g_Pl[o + j]);
    }
}

// ---------------- top-16 by score (warp per row) ----------------
__global__ __launch_bounds__(256)
void topk_kernel() {
    const int tid = threadIdx.x, lane = tid & 31, w = tid >> 5;
    const int n = blockIdx.x * 8 + w;
    const float* srow = g_S + (size_t)n * N_;
    float cand[16];
#pragma unroll
    for (int s = 0; s < 16; s++) cand[s] = srow[s * 32 + lane];
    const int base = n & ~511;
    unsigned used = 0;
    for (int sel = 0; sel < K_; sel++) {
        float best = -INFINITY;
        int bslot = -1;
#pragma unroll
        for (int s = 0; s < 16; s++)
            if (!((used >> s) & 1u) && cand[s] > best) { best = cand[s]; bslot = s; }
        int   bm = (bslot >= 0) ? ((bslot << 5) | lane) : 0x3fffffff;
        float bv = best;
#pragma unroll
        for (int off = 16; off; off >>= 1) {
            float ov = __shfl_xor_sync(0xffffffffu, bv, off);
            int   om = __shfl_xor_sync(0xffffffffu, bm, off);
            if (ov > bv || (ov == bv && om < bm)) { bv = ov; bm = om; }
        }
        if ((bm & 31) == lane && (bm >> 5) < 16) used |= 1u << (bm >> 5);
        if (lane == 0) g_IDX[(size_t)n * K_ + sel] = base + bm;
    }
}

// ---------------- gather-max + layernorm + selu ----------------
__global__ __launch_bounds__(256)
void final_kernel(const float* __restrict__ bc, const float* __restrict__ lnsc,
                  const float* __restrict__ lnbi, float* __restrict__ out) {
    const int n = blockIdx.x;
    const int o = threadIdx.x;
    const int lane = o & 31, w = o >> 5;
    __shared__ int   sidx[K_];
    __shared__ float red[8];
    __shared__ float sstat;
    if (o < K_) sidx[o] = g_IDX[n * K_ + o];
    __syncthreads();
    float v = -INFINITY;
#pragma unroll
    for (int k = 0; k < K_; k++) v = fmaxf(v, g_ZG[(size_t)sidx[k] * 512 + o]);
    float y = v + g_ZG[(size_t)n * 512 + OUT_ + o] + bc[o];
    float s = y;
#pragma unroll
    for (int off = 16; off; off >>= 1) s += __shfl_xor_sync(0xffffffffu, s, off);
    if (lane == 0) red[w] = s;
    __syncthreads();
    if (o == 0) {
        float t = 0.f;
        for (int i = 0; i < 8; i++) t += red[i];
        sstat = t * (1.f / OUT_);
    }
    __syncthreads();
    const float mu = sstat;
    float d = y - mu;
    s = d * d;
#pragma unroll
    for (int off = 16; off; off >>= 1) s += __shfl_xor_sync(0xffffffffu, s, off);
    if (lane == 0) red[w] = s;
    __syncthreads();
    if (o == 0) {
        float t = 0.f;
        for (int i = 0; i < 8; i++) t += red[i];
        sstat = t * (1.f / OUT_);
    }
    __syncthreads();
    const float var = sstat;
    float nv = d * rsqrtf(var + 1e-5f) * lnsc[o] + lnbi[o];
    float r = nv > 0.f ? 1.0507009873554805f * nv
                       : 1.7580993408473766f * expm1f(nv);
    out[(size_t)n * OUT_ + o] = r;
}

// ---------------- launcher ----------------
extern "C" void kernel_launch(void* const* d_in, const int* in_sizes, int n_in,
                              void* d_out, int out_size) {
    const float* obj = (const float*)d_in[0];
    const float* Wq  = (const float*)d_in[2];
    const float* bq  = (const float*)d_in[3];
    const float* Wk  = (const float*)d_in[4];
    const float* bk  = (const float*)d_in[5];
    const float* Wv  = (const float*)d_in[6];
    const float* bv  = (const float*)d_in[7];
    const float* Wr  = (const float*)d_in[8];
    const float* br  = (const float*)d_in[9];
    const float* Wc  = (const float*)d_in[10];
    const float* bc  = (const float*)d_in[11];
    const float* lns = (const float*)d_in[12];
    const float* lnb = (const float*)d_in[13];
    float* out = (float*)d_out;

    cudaFuncSetAttribute(mma_stage<0>, cudaFuncAttributeMaxDynamicSharedMemorySize, SM_BYTES);
    cudaFuncSetAttribute(mma_stage<1>, cudaFuncAttributeMaxDynamicSharedMemorySize, SM_BYTES);
    cudaFuncSetAttribute(mma_stage<2>, cudaFuncAttributeMaxDynamicSharedMemorySize, SM_BYTES);
    cudaFuncSetAttribute(mma_stage<3>, cudaFuncAttributeMaxDynamicSharedMemorySize, SM_BYTES);
    cudaFuncSetAttribute(mma_stage<4>, cudaFuncAttributeMaxDynamicSharedMemorySize, SM_BYTES);

    // 1) convert inputs / pack weights (bf16 hi/lo splits)
    convert_kernel<<<ROWS_ * IN_ / 256, 256>>>(obj, Wq, bq, Wk, bk, Wv, bv, Wr, br, Wc);
    // 2) QKVR = X @ W4 + bias  ->  Q,K splits; V transposed splits; R fp32
    mma_stage<0><<<dim3(4, 64, 1), 256, SM_BYTES>>>();
    // 3) S = Q K^T / sqrt(HID)
    mma_stage<1><<<dim3(4, 4, B_), 256, SM_BYTES>>>();
    // 4) softmax -> P bf16 splits
    softmax_kernel<<<ROWS_ / 8, 256>>>();
    // 5) H = P V + R (fp32 + splits)
    mma_stage<2><<<dim3(1, 4, B_), 256, SM_BYTES>>>();
    // 6) ||h||^2
    sqnorm_kernel<<<ROWS_ / 8, 256>>>();
    // 7) scores = 2 H H^T - ||h_m||^2
    mma_stage<3><<<dim3(4, 4, B_), 256, SM_BYTES>>>();
    // 8) top-16 neighbors
    topk_kernel<<<ROWS_ / 8, 256>>>();
    // 9) ZG = H @ [Wc2 | Wc1-Wc2]
    mma_stage<4><<<dim3(4, 64, 1), 256, SM_BYTES>>>();
    // 10) gather-max + LN + selu
    final_kernel<<<ROWS_, 256>>>(bc, lns, lnb, out);
}

// round 5
// speedup vs baseline: 2.0682x; 1.0830x over previous
#include <cuda_runtime.h>
#include <cuda_bf16.h>
#include <math.h>
#include <stdint.h>

#define B_    16
#define N_    512
#define IN_   256
#define HID_  128
#define OUT_  256
#define K_    16
#define ROWS_ (B_*N_)   // 8192

typedef __nv_bfloat16 bf16;

// ---------------- scratch (device globals; no runtime allocation) ----------------
__device__ __align__(128) bf16  g_Xh [ROWS_ * IN_],  g_Xl [ROWS_ * IN_];
__device__ __align__(128) bf16  g_W4h[512 * IN_],    g_W4l[512 * IN_];
__device__ __align__(128) bf16  g_WMh[512 * HID_],   g_WMl[512 * HID_];
__device__ __align__(128) float g_B4 [512];
__device__ __align__(128) bf16  g_Qh [ROWS_ * HID_], g_Ql [ROWS_ * HID_];
__device__ __align__(128) bf16  g_Kh [ROWS_ * HID_], g_Kl [ROWS_ * HID_];
__device__ __align__(128) bf16  g_VTh[B_ * HID_ * N_], g_VTl[B_ * HID_ * N_]; // [b][d][m]
__device__ __align__(128) float g_R  [ROWS_ * HID_];
__device__ __align__(128) float g_S  [B_ * N_ * N_];
__device__ __align__(128) bf16  g_Ph [B_ * N_ * N_], g_Pl [B_ * N_ * N_];
__device__ __align__(128) float g_H  [ROWS_ * HID_];
__device__ __align__(128) bf16  g_Hh [ROWS_ * HID_], g_Hl [ROWS_ * HID_];
__device__ __align__(128) float g_SQ [ROWS_];
__device__ __align__(128) int   g_IDX[ROWS_ * K_];
__device__ __align__(128) float g_ZG [ROWS_ * 512];

// ---------------- helpers ----------------
__device__ __forceinline__ uint32_t s2u(const void* p) {
    uint32_t a;
    asm("{ .reg .u64 t; cvta.to.shared.u64 t, %1; cvt.u32.u64 %0, t; }" : "=r"(a) : "l"(p));
    return a;
}
__device__ __forceinline__ void ldsm4(uint32_t* r, uint32_t addr) {
    asm volatile("ldmatrix.sync.aligned.m8n8.x4.shared.b16 {%0,%1,%2,%3}, [%4];"
                 : "=r"(r[0]), "=r"(r[1]), "=r"(r[2]), "=r"(r[3]) : "r"(addr));
}
__device__ __forceinline__ void ldsm2(uint32_t* r, uint32_t addr) {
    asm volatile("ldmatrix.sync.aligned.m8n8.x2.shared.b16 {%0,%1}, [%2];"
                 : "=r"(r[0]), "=r"(r[1]) : "r"(addr));
}
__device__ __forceinline__ void mma16816(float* c, const uint32_t* a, const uint32_t* b) {
    asm volatile("mma.sync.aligned.m16n8k16.row.col.f32.bf16.bf16.f32 "
                 "{%0,%1,%2,%3}, {%4,%5,%6,%7}, {%8,%9}, {%0,%1,%2,%3};"
                 : "+f"(c[0]), "+f"(c[1]), "+f"(c[2]), "+f"(c[3])
                 : "r"(a[0]), "r"(a[1]), "r"(a[2]), "r"(a[3]), "r"(b[0]), "r"(b[1]));
}
__device__ __forceinline__ void split2(float x, bf16& h, bf16& l) {
    h = __float2bfloat16_rn(x);
    l = __float2bfloat16_rn(x - __bfloat162float(h));
}
__device__ __forceinline__ void cpa16(uint32_t dst, const void* src) {
    asm volatile("cp.async.cg.shared.global [%0], [%1], 16;" :: "r"(dst), "l"(src));
}
__device__ __forceinline__ void cpa_commit() {
    asm volatile("cp.async.commit_group;" ::: "memory");
}
template <int NN> __device__ __forceinline__ void cpa_wait() {
    asm volatile("cp.async.wait_group %0;" :: "n"(NN) : "memory");
}

// ---------------- input conversion / weight packing ----------------
__global__ void convert_kernel(const float* __restrict__ X,
                               const float* __restrict__ Wq, const float* __restrict__ bq,
                               const float* __restrict__ Wk, const float* __restrict__ bk,
                               const float* __restrict__ Wv, const float* __restrict__ bv,
                               const float* __restrict__ Wr, const float* __restrict__ br,
                               const float* __restrict__ Wc) {
    int t = blockIdx.x * blockDim.x + threadIdx.x;
    if (t < ROWS_ * IN_) split2(X[t], g_Xh[t], g_Xl[t]);
    if (t < 512 * IN_) {
        int o = t >> 8, i = t & 255;
        int blk = o >> 7, h = o & 127;
        const float* W = (blk == 0) ? Wq : (blk == 1) ? Wk : (blk == 2) ? Wv : Wr;
        split2(W[i * HID_ + h], g_W4h[t], g_W4l[t]);
    }
    if (t < 512) {
        int blk = t >> 7, h = t & 127;
        const float* sb = (blk == 0) ? bq : (blk == 1) ? bk : (blk == 2) ? bv : br;
        g_B4[t] = sb[h];
    }
    if (t < 512 * HID_) {
        int o = t >> 7, d = t & 127;
        float w2 = Wc[(HID_ + d) * OUT_ + (o & 255)];
        float v  = (o < OUT_) ? w2 : (Wc[d * OUT_ + (o - OUT_)] - w2);
        split2(v, g_WMh[t], g_WMl[t]);
    }
}

// ---------------- unified mma.sync stage (double-buffered cp.async) ----------------
// D[128x128] = A[128xK] * B[128xK]^T with bf16x3 splits, fp32 register accumulate.
// MODE: 0=QKVR  1=S  2=AV(+sqnorm)  3=GRAM  4=ZG
#define BK      64
#define LDS_    72                       // BK + 8 pad (bf16)
#define TILEB   (128 * LDS_ * 2)         // 18432 bytes per tile
#define STAGEB  (4 * TILEB)              // 73728 per pipeline stage
#define SM_BYTES (2 * STAGEB + 2048)     // + sqnorm reduce scratch

__device__ __forceinline__ void compute_chunk(
    uint32_t uAh, uint32_t uAl, uint32_t uBh, uint32_t uBl,
    float (&acc)[4][4][4], int lane, int wm, int wn) {
    const int arow = wm * 64 + (lane & 15);
    const int akof = ((lane >> 4) << 3);
    const int brow = wn * 32 + (lane & 7);
    const int bkof = ((lane >> 3) & 1) << 3;
#pragma unroll
    for (int ks = 0; ks < BK / 16; ks++) {
        const int kk = ks * 16;
        uint32_t aH[4][4], aL[4][4], bH[4][2], bL[4][2];
#pragma unroll
        for (int i = 0; i < 4; i++)
            ldsm4(aH[i], uAh + (uint32_t)(((arow + i * 16) * LDS_ + kk + akof) * 2));
#pragma unroll
        for (int j = 0; j < 4; j++)
            ldsm2(bH[j], uBh + (uint32_t)(((brow + j * 8) * LDS_ + kk + bkof) * 2));
#pragma unroll
        for (int i = 0; i < 4; i++)
#pragma unroll
            for (int j = 0; j < 4; j++) mma16816(acc[i][j], aH[i], bH[j]);
#pragma unroll
        for (int i = 0; i < 4; i++)
            ldsm4(aL[i], uAl + (uint32_t)(((arow + i * 16) * LDS_ + kk + akof) * 2));
#pragma unroll
        for (int i = 0; i < 4; i++)
#pragma unroll
            for (int j = 0; j < 4; j++) mma16816(acc[i][j], aL[i], bH[j]);
#pragma unroll
        for (int j = 0; j < 4; j++)
            ldsm2(bL[j], uBl + (uint32_t)(((brow + j * 8) * LDS_ + kk + bkof) * 2));
#pragma unroll
        for (int i = 0; i < 4; i++)
#pragma unroll
            for (int j = 0; j < 4; j++) mma16816(acc[i][j], aH[i], bL[j]);
    }
}

template <int MODE>
__global__ void __launch_bounds__(256, 1) mma_stage() {
    extern __shared__ char smem[];
    const int tid = threadIdx.x, lane = tid & 31, w = tid >> 5;
    const int wm = w & 1, wn = w >> 1;
    const int nT = blockIdx.x, mT = blockIdx.y, b = blockIdx.z;

    const bf16 *Ah, *Al, *Bh, *Bl;
    int lda, ldb;
    constexpr int Kd = (MODE == 0) ? IN_ : (MODE == 2) ? N_ : HID_;
    constexpr int nc = Kd / BK;
    if (MODE == 0) {
        size_t ar = (size_t)mT * 128 * IN_;
        Ah = g_Xh + ar; Al = g_Xl + ar; lda = IN_;
        size_t br_ = (size_t)nT * 128 * IN_;
        Bh = g_W4h + br_; Bl = g_W4l + br_; ldb = IN_;
    } else if (MODE == 1) {
        size_t ar = ((size_t)b * N_ + mT * 128) * HID_;
        Ah = g_Qh + ar; Al = g_Ql + ar; lda = HID_;
        size_t br_ = ((size_t)b * N_ + nT * 128) * HID_;
        Bh = g_Kh + br_; Bl = g_Kl + br_; ldb = HID_;
    } else if (MODE == 2) {
        size_t ar = ((size_t)b * N_ + mT * 128) * N_;
        Ah = g_Ph + ar; Al = g_Pl + ar; lda = N_;
        size_t br_ = (size_t)b * HID_ * N_;
        Bh = g_VTh + br_; Bl = g_VTl + br_; ldb = N_;
    } else if (MODE == 3) {
        size_t ar = ((size_t)b * N_ + mT * 128) * HID_;
        Ah = g_Hh + ar; Al = g_Hl + ar; lda = HID_;
        size_t br_ = ((size_t)b * N_ + nT * 128) * HID_;
        Bh = g_Hh + br_; Bl = g_Hl + br_; ldb = HID_;
    } else {
        size_t ar = (size_t)mT * 128 * HID_;
        Ah = g_Hh + ar; Al = g_Hl + ar; lda = HID_;
        size_t br_ = (size_t)nT * 128 * HID_;
        Bh = g_WMh + br_; Bl = g_WMl + br_; ldb = HID_;
    }

    const uint32_t ubase = s2u(smem);

    // async chunk loader: 16 cp.async x4 tiles per thread
    auto load_chunk = [&](int c, int s) {
        const int k0 = c * BK;
        const uint32_t ub = ubase + s * STAGEB;
#pragma unroll
        for (int i = 0; i < 4; i++) {
            int idx = tid + i * 256;
            int r = idx >> 3, c8 = (idx & 7) << 3;
            uint32_t sdst = (uint32_t)((r * LDS_ + c8) * 2);
            cpa16(ub + sdst,             Ah + (size_t)r * lda + k0 + c8);
            cpa16(ub + TILEB + sdst,     Al + (size_t)r * lda + k0 + c8);
            cpa16(ub + 2 * TILEB + sdst, Bh + (size_t)r * ldb + k0 + c8);
            cpa16(ub + 3 * TILEB + sdst, Bl + (size_t)r * ldb + k0 + c8);
        }
        cpa_commit();
    };

    float acc[4][4][4] = {};

    load_chunk(0, 0);
#pragma unroll
    for (int c = 0; c < nc; c++) {
        if (c + 1 < nc) load_chunk(c + 1, (c + 1) & 1);
        if (c + 1 < nc) cpa_wait<1>(); else cpa_wait<0>();
        __syncthreads();
        const uint32_t ub = ubase + (c & 1) * STAGEB;
        compute_chunk(ub, ub + TILEB, ub + 2 * TILEB, ub + 3 * TILEB, acc, lane, wm, wn);
        __syncthreads();
    }

    // ---------------- epilogue ----------------
    const int r_base = wm * 64 + (lane >> 2);
    const int c_base = wn * 32 + ((lane & 3) << 1);

    if (MODE == 0 && nT == 2) {
        float* Cs = (float*)smem;   // [128][129]
#pragma unroll
        for (int i = 0; i < 4; i++)
#pragma unroll
            for (int j = 0; j < 4; j++) {
                int r = r_base + i * 16, c = c_base + j * 8;
                Cs[r * 129 + c]           = acc[i][j][0] + g_B4[256 + c];
                Cs[r * 129 + c + 1]       = acc[i][j][1] + g_B4[256 + c + 1];
                Cs[(r + 8) * 129 + c]     = acc[i][j][2] + g_B4[256 + c];
                Cs[(r + 8) * 129 + c + 1] = acc[i][j][3] + g_B4[256 + c + 1];
            }
        __syncthreads();
        const int bb = mT >> 2, m0 = (mT & 3) * 128;
        const int d = tid >> 1, ms = (tid & 1) * 64;
        size_t base = ((size_t)bb * HID_ + d) * N_ + m0 + ms;
#pragma unroll 8
        for (int k = 0; k < 64; k++)
            split2(Cs[(ms + k) * 129 + d], g_VTh[base + k], g_VTl[base + k]);
        return;
    }

    float rsq[4][2] = {};
#pragma unroll
    for (int i = 0; i < 4; i++)
#pragma unroll
        for (int j = 0; j < 4; j++)
#pragma unroll
            for (int h = 0; h < 2; h++) {
                const int r = r_base + i * 16 + h * 8;
                const int c = c_base + j * 8;
                float v0 = acc[i][j][h * 2], v1 = acc[i][j][h * 2 + 1];
                if (MODE == 0) {
                    size_t grow = (size_t)mT * 128 + r;
                    if (nT == 0 || nT == 1) {
                        bf16* Dh = (nT == 0) ? g_Qh : g_Kh;
                        bf16* Dl = (nT == 0) ? g_Ql : g_Kl;
                        split2(v0 + g_B4[nT * 128 + c],     Dh[grow * HID_ + c],     Dl[grow * HID_ + c]);
                        split2(v1 + g_B4[nT * 128 + c + 1], Dh[grow * HID_ + c + 1], Dl[grow * HID_ + c + 1]);
                    } else {   // nT == 3 -> R
                        *(float2*)(g_R + grow * HID_ + c) =
                            make_float2(v0 + g_B4[384 + c], v1 + g_B4[384 + c + 1]);
                    }
                } else if (MODE == 1) {
                    size_t row = (size_t)b * N_ + mT * 128 + r;
                    *(float2*)(g_S + row * N_ + nT * 128 + c) =
                        make_float2(v0 * 0.08838834764831843f, v1 * 0.08838834764831843f);
                } else if (MODE == 2) {
                    size_t row = (size_t)b * N_ + mT * 128 + r;
                    float h0 = v0 + g_R[row * HID_ + c];
                    float h1 = v1 + g_R[row * HID_ + c + 1];
                    *(float2*)(g_H + row * HID_ + c) = make_float2(h0, h1);
                    split2(h0, g_Hh[row * HID_ + c],     g_Hl[row * HID_ + c]);
                    split2(h1, g_Hh[row * HID_ + c + 1], g_Hl[row * HID_ + c + 1]);
                    rsq[i][h] = fmaf(h0, h0, fmaf(h1, h1, rsq[i][h]));
                } else if (MODE == 3) {
                    size_t row = (size_t)b * N_ + mT * 128 + r;
                    float s0 = 2.f * v0 - g_SQ[b * N_ + nT * 128 + c];
                    float s1 = 2.f * v1 - g_SQ[b * N_ + nT * 128 + c + 1];
                    *(float2*)(g_S + row * N_ + nT * 128 + c) = make_float2(s0, s1);
                } else {
                    size_t row = (size_t)mT * 128 + r;
                    *(float2*)(g_ZG + row * 512 + nT * 128 + c) = make_float2(v0, v1);
                }
            }

    if (MODE == 2) {
        // cross-warp ||h||^2 reduction: sq_s[wn][row]
        float* sq_s = (float*)(smem + 2 * STAGEB);
        __syncthreads();
#pragma unroll
        for (int i = 0; i < 4; i++)
#pragma unroll
            for (int h = 0; h < 2; h++) {
                float v = rsq[i][h];
                v += __shfl_xor_sync(0xffffffffu, v, 1);
                v += __shfl_xor_sync(0xffffffffu, v, 2);
                if ((lane & 3) == 0) {
                    int r = r_base + i * 16 + h * 8;
                    sq_s[wn * 128 + r] = v;
                }
            }
        __syncthreads();
        if (tid < 128)
            g_SQ[(size_t)b * N_ + mT * 128 + tid] =
                sq_s[tid] + sq_s[128 + tid] + sq_s[256 + tid] + sq_s[384 + tid];
    }
}

// ---------------- softmax: S -> P (bf16 hi/lo), warp per row ----------------
__global__ __launch_bounds__(256)
void softmax_kernel() {
    const int tid = threadIdx.x, lane = tid & 31, w = tid >> 5;
    const size_t row = (size_t)blockIdx.x * 8 + w;
    const float* srow = g_S + row * N_;
    float v[16];
    float mx = -INFINITY;
#pragma unroll
    for (int i = 0; i < 4; i++) {
        float4 t = *(const float4*)(srow + i * 128 + lane * 4);
        v[4*i+0] = t.x; v[4*i+1] = t.y; v[4*i+2] = t.z; v[4*i+3] = t.w;
        mx = fmaxf(mx, fmaxf(fmaxf(t.x, t.y), fmaxf(t.z, t.w)));
    }
#pragma unroll
    for (int off = 16; off; off >>= 1) mx = fmaxf(mx, __shfl_xor_sync(0xffffffffu, mx, off));
    float sum = 0.f;
#pragma unroll
    for (int i = 0; i < 16; i++) { v[i] = __expf(v[i] - mx); sum += v[i]; }
#pragma unroll
    for (int off = 16; off; off >>= 1) sum += __shfl_xor_sync(0xffffffffu, sum, off);
    float inv = 1.f / sum;
#pragma unroll
    for (int i = 0; i < 16; i++) v[i] *= inv;
#pragma unroll
    for (int i = 0; i < 4; i++) {
        size_t o = row * N_ + i * 128 + lane * 4;
#pragma unroll
        for (int j = 0; j < 4; j++) split2(v[4*i+j], g_Ph[o + j], g_Pl[o + j]);
    }
}

// ---------------- top-16 by score (warp per row) ----------------
__global__ __launch_bounds__(256)
void topk_kernel() {
    const int tid = threadIdx.x, lane = tid & 31, w = tid >> 5;
    const int n = blockIdx.x * 8 + w;
    const float* srow = g_S + (size_t)n * N_;
    float cand[16];
#pragma unroll
    for (int s = 0; s < 16; s++) cand[s] = srow[s * 32 + lane];
    const int base = n & ~511;
    unsigned used = 0;
    for (int sel = 0; sel < K_; sel++) {
        float best = -INFINITY;
        int bslot = -1;
#pragma unroll
        for (int s = 0; s < 16; s++)
            if (!((used >> s) & 1u) && cand[s] > best) { best = cand[s]; bslot = s; }
        int   bm = (bslot >= 0) ? ((bslot << 5) | lane) : 0x3fffffff;
        float bv = best;
#pragma unroll
        for (int off = 16; off; off >>= 1) {
            float ov = __shfl_xor_sync(0xffffffffu, bv, off);
            int   om = __shfl_xor_sync(0xffffffffu, bm, off);
            if (ov > bv || (ov == bv && om < bm)) { bv = ov; bm = om; }
        }
        if ((bm & 31) == lane && (bm >> 5) < 16) used |= 1u << (bm >> 5);
        if (lane == 0) g_IDX[(size_t)n * K_ + sel] = base + bm;
    }
}

// ---------------- gather-max + layernorm + selu ----------------
__global__ __launch_bounds__(256)
void final_kernel(const float* __restrict__ bc, const float* __restrict__ lnsc,
                  const float* __restrict__ lnbi, float* __restrict__ out) {
    const int n = blockIdx.x;
    const int o = threadIdx.x;
    const int lane = o & 31, w = o >> 5;
    __shared__ int   sidx[K_];
    __shared__ float red[8];
    __shared__ float sstat;
    if (o < K_) sidx[o] = g_IDX[n * K_ + o];
    __syncthreads();
    float v = -INFINITY;
#pragma unroll
    for (int k = 0; k < K_; k++) v = fmaxf(v, g_ZG[(size_t)sidx[k] * 512 + o]);
    float y = v + g_ZG[(size_t)n * 512 + OUT_ + o] + bc[o];
    float s = y;
#pragma unroll
    for (int off = 16; off; off >>= 1) s += __shfl_xor_sync(0xffffffffu, s, off);
    if (lane == 0) red[w] = s;
    __syncthreads();
    if (o == 0) {
        float t = 0.f;
        for (int i = 0; i < 8; i++) t += red[i];
        sstat = t * (1.f / OUT_);
    }
    __syncthreads();
    const float mu = sstat;
    float d = y - mu;
    s = d * d;
#pragma unroll
    for (int off = 16; off; off >>= 1) s += __shfl_xor_sync(0xffffffffu, s, off);
    if (lane == 0) red[w] = s;
    __syncthreads();
    if (o == 0) {
        float t = 0.f;
        for (int i = 0; i < 8; i++) t += red[i];
        sstat = t * (1.f / OUT_);
    }
    __syncthreads();
    const float var = sstat;
    float nv = d * rsqrtf(var + 1e-5f) * lnsc[o] + lnbi[o];
    float r = nv > 0.f ? 1.0507009873554805f * nv
                       : 1.7580993408473766f * expm1f(nv);
    out[(size_t)n * OUT_ + o] = r;
}

// ---------------- launcher ----------------
extern "C" void kernel_launch(void* const* d_in, const int* in_sizes, int n_in,
                              void* d_out, int out_size) {
    const float* obj = (const float*)d_in[0];
    const float* Wq  = (const float*)d_in[2];
    const float* bq  = (const float*)d_in[3];
    const float* Wk  = (const float*)d_in[4];
    const float* bk  = (const float*)d_in[5];
    const float* Wv  = (const float*)d_in[6];
    const float* bv  = (const float*)d_in[7];
    const float* Wr  = (const float*)d_in[8];
    const float* br  = (const float*)d_in[9];
    const float* Wc  = (const float*)d_in[10];
    const float* bc  = (const float*)d_in[11];
    const float* lns = (const float*)d_in[12];
    const float* lnb = (const float*)d_in[13];
    float* out = (float*)d_out;

    cudaFuncSetAttribute(mma_stage<0>, cudaFuncAttributeMaxDynamicSharedMemorySize, SM_BYTES);
    cudaFuncSetAttribute(mma_stage<1>, cudaFuncAttributeMaxDynamicSharedMemorySize, SM_BYTES);
    cudaFuncSetAttribute(mma_stage<2>, cudaFuncAttributeMaxDynamicSharedMemorySize, SM_BYTES);
    cudaFuncSetAttribute(mma_stage<3>, cudaFuncAttributeMaxDynamicSharedMemorySize, SM_BYTES);
    cudaFuncSetAttribute(mma_stage<4>, cudaFuncAttributeMaxDynamicSharedMemorySize, SM_BYTES);

    // 1) convert inputs / pack weights (bf16 hi/lo splits)
    convert_kernel<<<ROWS_ * IN_ / 256, 256>>>(obj, Wq, bq, Wk, bk, Wv, bv, Wr, br, Wc);
    // 2) QKVR = X @ W4 + bias  ->  Q,K splits; V transposed splits; R fp32
    mma_stage<0><<<dim3(4, 64, 1), 256, SM_BYTES>>>();
    // 3) S = Q K^T / sqrt(HID)
    mma_stage<1><<<dim3(4, 4, B_), 256, SM_BYTES>>>();
    // 4) softmax -> P bf16 splits
    softmax_kernel<<<ROWS_ / 8, 256>>>();
    // 5) H = P V + R (fp32 + splits) ; fused ||h||^2
    mma_stage<2><<<dim3(1, 4, B_), 256, SM_BYTES>>>();
    // 6) scores = 2 H H^T - ||h_m||^2
    mma_stage<3><<<dim3(4, 4, B_), 256, SM_BYTES>>>();
    // 7) top-16 neighbors
    topk_kernel<<<ROWS_ / 8, 256>>>();
    // 8) ZG = H @ [Wc2 | Wc1-Wc2]
    mma_stage<4><<<dim3(4, 64, 1), 256, SM_BYTES>>>();
    // 9) gather-max + LN + selu
    final_kernel<<<ROWS_, 256>>>(bc, lns, lnb, out);
}